// round 16
// baseline (speedup 1.0000x reference)
#include <cuda_runtime.h>
#include <cuda_fp16.h>
#include <math.h>

#define BB 2
#define TT 2048
#define DD 1024
#define HH 16
#define HD 64
#define MTOT (BB * TT)          // 4096 rows

// Scratch (device globals — no runtime allocation allowed). All half.
__device__ __half g_xh[(size_t)MTOT * DD];          // half(x)
__device__ __half g_qh[(size_t)MTOT * DD];          // half(q * 0.125*log2e)
__device__ __half g_wTh[(size_t)(2 * DD) * DD];     // half(kv_w)^T  [2048][1024]
__device__ __half g_owTh[(size_t)DD * DD];          // half(out_w)^T [1024][1024]
__device__ __half g_kvh[(size_t)MTOT * 2 * DD];     // [4096][2048] (k|v) half
__device__ __half g_vTh[(size_t)BB * HH * HD * TT]; // [bh][d][kv] half
__device__ __half g_attnh[(size_t)MTOT * DD];       // attention out, half

// ---------------------------------------------------------------------------
// helpers (baseline PTX only)
// ---------------------------------------------------------------------------
__device__ __forceinline__ void mma_f16(float c[4], const unsigned a[4],
                                        const unsigned b0, const unsigned b1) {
    asm volatile(
        "mma.sync.aligned.m16n8k16.row.col.f32.f16.f16.f32 "
        "{%0,%1,%2,%3}, {%4,%5,%6,%7}, {%8,%9}, {%0,%1,%2,%3};"
        : "+f"(c[0]), "+f"(c[1]), "+f"(c[2]), "+f"(c[3])
        : "r"(a[0]), "r"(a[1]), "r"(a[2]), "r"(a[3]),
          "r"(b0), "r"(b1));
}

__device__ __forceinline__ void ldsm_x4(unsigned r[4], unsigned saddr) {
    asm volatile("ldmatrix.sync.aligned.m8n8.x4.shared.b16 {%0,%1,%2,%3}, [%4];"
                 : "=r"(r[0]), "=r"(r[1]), "=r"(r[2]), "=r"(r[3]) : "r"(saddr));
}

__device__ __forceinline__ float ex2f(float x) {
    float y;
    asm("ex2.approx.f32 %0, %1;" : "=f"(y) : "f"(x));
    return y;
}

__device__ __forceinline__ void cp16(void* smem_ptr, const void* gmem) {
    unsigned s = (unsigned)__cvta_generic_to_shared(smem_ptr);
    asm volatile("cp.async.cg.shared.global [%0], [%1], 16;"
                 :: "r"(s), "l"(gmem) : "memory");
}
#define CP_COMMIT() asm volatile("cp.async.commit_group;" ::: "memory")
#define CP_WAIT(n)  asm volatile("cp.async.wait_group %0;" :: "n"(n) : "memory")

// ---------------------------------------------------------------------------
// fused f32 -> f16 conversion: first n4 float4s from inA (scale 1),
// next n4 from inB (scale sc).
// ---------------------------------------------------------------------------
__global__ __launch_bounds__(256) void conv2_kernel(
    const float* __restrict__ inA, __half* __restrict__ outA,
    const float* __restrict__ inB, __half* __restrict__ outB,
    int n4, float sc)
{
    int i = blockIdx.x * blockDim.x + threadIdx.x;
    if (i < n4) {
        float4 v = reinterpret_cast<const float4*>(inA)[i];
        reinterpret_cast<__half2*>(outA)[2 * i] = __floats2half2_rn(v.x, v.y);
        reinterpret_cast<__half2*>(outA)[2 * i + 1] = __floats2half2_rn(v.z, v.w);
    } else if (i < 2 * n4) {
        int j = i - n4;
        float4 v = reinterpret_cast<const float4*>(inB)[j];
        reinterpret_cast<__half2*>(outB)[2 * j] =
            __floats2half2_rn(v.x * sc, v.y * sc);
        reinterpret_cast<__half2*>(outB)[2 * j + 1] =
            __floats2half2_rn(v.z * sc, v.w * sc);
    }
}

// fused transpose+convert for both weights: blockIdx.x < CA/32 -> A (R x CA),
// else B (R x CB). out[c][r] = half(in[r][c]).
__global__ __launch_bounds__(256) void convT2_kernel(
    const float* __restrict__ inA, __half* __restrict__ outA, int CA,
    const float* __restrict__ inB, __half* __restrict__ outB, int CB, int R)
{
    __shared__ float tb[32][33];
    const float* in;
    __half* out;
    int c0, C;
    if ((int)blockIdx.x < CA / 32) {
        in = inA; out = outA; C = CA; c0 = blockIdx.x * 32;
    } else {
        in = inB; out = outB; C = CB; c0 = (blockIdx.x - CA / 32) * 32;
    }
    const int r0 = blockIdx.y * 32;
    const int tx = threadIdx.x, ty = threadIdx.y;
#pragma unroll
    for (int i = 0; i < 32; i += 8)
        tb[ty + i][tx] = in[(size_t)(r0 + ty + i) * C + c0 + tx];
    __syncthreads();
#pragma unroll
    for (int i = 0; i < 32; i += 8)
        out[(size_t)(c0 + ty + i) * R + r0 + tx] = __float2half_rn(tb[tx][ty + i]);
}

// ---------------------------------------------------------------------------
// fp16 mma GEMM: C[M,N] = A[M,K] @ Bt[N,K]^T + bias[N]
// CTA 128x128, 8 warps (2m x 4n), warp tile 64x32, K-step 64 halves.
// 3-stage cp.async pipeline, ONE __syncthreads per K-tile.
// ---------------------------------------------------------------------------
#define AH 72
#define GEMM_SMEM (6 * 128 * AH * sizeof(__half))   // 108KB

__global__ __launch_bounds__(256) void gemm_h_kernel(
    const __half* __restrict__ A, const __half* __restrict__ Bt,
    const float* __restrict__ bias, float* __restrict__ Cf,
    __half* __restrict__ Ch, int M, int N, int K, int out_half)
{
    extern __shared__ __align__(16) __half hsm[];
    const unsigned smem0 = (unsigned)__cvta_generic_to_shared(hsm);

    const int tid  = threadIdx.x;
    const int lane = tid & 31;
    const int wid  = tid >> 5;
    const int g = lane >> 2;
    const int t = lane & 3;

    const int row0 = blockIdx.y * 128;
    const int col0 = blockIdx.x * 128;
    const int warp_m = (wid & 1) * 64;
    const int warp_n = (wid >> 1) * 32;

    const unsigned a_off =
        (((lane & 7) + ((lane & 8) ? 8 : 0)) * AH + ((lane & 16) ? 8 : 0)) * 2;
    const unsigned b4_off =
        (((lane & 7) + ((lane & 16) ? 8 : 0)) * AH + ((lane & 8) ? 8 : 0)) * 2;

    float acc[4][4][4];
#pragma unroll
    for (int mi = 0; mi < 4; mi++)
#pragma unroll
        for (int ni = 0; ni < 4; ni++)
#pragma unroll
            for (int k = 0; k < 4; k++) acc[mi][ni][k] = 0.f;

    const int NT = K >> 6;

    auto stage = [&](int kt, int bf) {
        const int kb = kt << 6;
        __half* as = hsm + bf * 128 * AH;
        __half* bs = hsm + (3 + bf) * 128 * AH;
#pragma unroll
        for (int i = 0; i < 4; i++) {
            const int idx = i * 256 + tid;
            const int r = idx >> 3, c = idx & 7;
            cp16(&as[r * AH + c * 8], A + (size_t)(row0 + r) * K + kb + c * 8);
        }
#pragma unroll
        for (int i = 0; i < 4; i++) {
            const int idx = i * 256 + tid;
            const int r = idx >> 3, c = idx & 7;
            cp16(&bs[r * AH + c * 8], Bt + (size_t)(col0 + r) * K + kb + c * 8);
        }
        CP_COMMIT();
    };

    stage(0, 0);
    stage(1, 1);

    int bf = 0, bf2 = 2;
    for (int kt = 0; kt < NT; kt++) {
        if (kt + 1 < NT) { CP_WAIT(1); } else { CP_WAIT(0); }
        __syncthreads();
        if (kt + 2 < NT) stage(kt + 2, bf2);

        const unsigned asu = smem0 + bf * (128 * AH * 2);
        const unsigned bsu = smem0 + (3 + bf) * (128 * AH * 2);

#pragma unroll
        for (int s = 0; s < 4; s++) {
            const unsigned kb2 = s * 16 * 2;
            unsigned afr[4][4];
#pragma unroll
            for (int mi = 0; mi < 4; mi++)
                ldsm_x4(afr[mi],
                        asu + (warp_m + mi * 16) * AH * 2 + kb2 + a_off);
            unsigned bfr[2][4];
#pragma unroll
            for (int np = 0; np < 2; np++)
                ldsm_x4(bfr[np],
                        bsu + (warp_n + np * 16) * AH * 2 + kb2 + b4_off);
#pragma unroll
            for (int mi = 0; mi < 4; mi++)
#pragma unroll
                for (int ni = 0; ni < 4; ni++)
                    mma_f16(acc[mi][ni], afr[mi],
                            bfr[ni >> 1][(ni & 1) * 2],
                            bfr[ni >> 1][(ni & 1) * 2 + 1]);
        }
        bf = (bf == 2) ? 0 : bf + 1;
        bf2 = (bf2 == 2) ? 0 : bf2 + 1;
    }

#pragma unroll
    for (int ni = 0; ni < 4; ni++) {
        const int col = col0 + warp_n + ni * 8 + 2 * t;
        const float b0 = bias[col], b1 = bias[col + 1];
#pragma unroll
        for (int mi = 0; mi < 4; mi++) {
            const int row = row0 + warp_m + mi * 16 + g;
            float v00 = acc[mi][ni][0] + b0, v01 = acc[mi][ni][1] + b1;
            float v10 = acc[mi][ni][2] + b0, v11 = acc[mi][ni][3] + b1;
            if (out_half) {
                *reinterpret_cast<__half2*>(Ch + (size_t)row * N + col) =
                    __floats2half2_rn(v00, v01);
                *reinterpret_cast<__half2*>(Ch + (size_t)(row + 8) * N + col) =
                    __floats2half2_rn(v10, v11);
            } else {
                *reinterpret_cast<float2*>(Cf + (size_t)row * N + col) =
                    make_float2(v00, v01);
                *reinterpret_cast<float2*>(Cf + (size_t)(row + 8) * N + col) =
                    make_float2(v10, v11);
            }
        }
    }
}

// ---------------------------------------------------------------------------
// V transpose (half): g_vTh[bh][d][kv] = g_kvh[b*TT+kv][DD + h*HD + d]
// ---------------------------------------------------------------------------
__global__ __launch_bounds__(256) void vtrans_kernel()
{
    __shared__ __half t[32][34];
    const int kv0 = blockIdx.x * 32;
    const int bh  = blockIdx.y >> 1;
    const int d0  = (blockIdx.y & 1) * 32;
    const int b   = bh >> 4;
    const int h   = bh & 15;
    const int tx = threadIdx.x, ty = threadIdx.y;

#pragma unroll
    for (int i = 0; i < 32; i += 8)
        t[ty + i][tx] = g_kvh[(size_t)(b * TT + kv0 + ty + i) * (2 * DD)
                              + DD + h * HD + d0 + tx];
    __syncthreads();
#pragma unroll
    for (int i = 0; i < 32; i += 8)
        g_vTh[(size_t)(bh * HD + d0 + ty + i) * TT + kv0 + tx] = t[tx][ty + i];
}

// ---------------------------------------------------------------------------
// fp16 mma flash attention: register-resident P, hoisted Q fragments,
// no-max softmax (p = 2^s), l via ones-column MMA, 128-key big tiles,
// paired-x4 B loads, cp.async double buffer, ONE sync per tile.
// Grid: (Tq/128, B*H). 8 warps; warp w owns q rows [16w,16w+16).
// ---------------------------------------------------------------------------
#define SPH 72
#define ATTN_SMEM ((size_t)(128 + 256 + 256) * SPH * sizeof(__half))

__global__ __launch_bounds__(256) void attn_h_kernel()
{
    extern __shared__ __align__(16) __half sm[];
    __half* Qs      = sm;                     // [128][SPH]
    __half* Ksb[2]  = {Qs + 128 * SPH, Qs + 256 * SPH};   // each [128][SPH]
    __half* Vtsb[2] = {Qs + 384 * SPH, Qs + 512 * SPH};   // each [128][SPH]
    const unsigned smem0 = (unsigned)__cvta_generic_to_shared(sm);

    const int bh = blockIdx.y;
    const int b  = bh >> 4;
    const int h  = bh & 15;
    const int q0 = blockIdx.x * 128;

    const int tid  = threadIdx.x;
    const int wid  = tid >> 5;
    const int lane = tid & 31;
    const int g = lane >> 2;
    const int t = lane & 3;
    const int qr = wid * 16;

    const unsigned a_off =
        (((lane & 7) + ((lane & 8) ? 8 : 0)) * SPH + ((lane & 16) ? 8 : 0)) * 2;
    const unsigned b4_off =
        (((lane & 7) + ((lane & 16) ? 8 : 0)) * SPH + ((lane & 8) ? 8 : 0)) * 2;

    const unsigned bone = (g == 0) ? 0x3C003C00u : 0u;

    // ---- stage Q tile (own cp.async group) ----
#pragma unroll
    for (int i = 0; i < 4; i++) {
        const int idx = i * 256 + tid;
        const int r = idx >> 3, c = idx & 7;
        cp16(&Qs[r * SPH + c * 8],
             g_qh + (size_t)(b * TT + q0 + r) * DD + h * HD + c * 8);
    }
    CP_COMMIT();

    auto stageKV = [&](int kt, int bf) {
        const int k0 = kt * 128;
#pragma unroll
        for (int i = 0; i < 4; i++) {
            const int idx = i * 256 + tid;
            const int r = idx >> 3, c = idx & 7;     // r: 0..127
            cp16(&Ksb[bf][r * SPH + c * 8],
                 g_kvh + (size_t)(b * TT + k0 + r) * (2 * DD) + h * HD + c * 8);
            const int d = r & 63, hf = r >> 6;
            cp16(&Vtsb[bf][r * SPH + c * 8],
                 g_vTh + (size_t)(bh * HD + d) * TT + k0 + hf * 64 + c * 8);
        }
        CP_COMMIT();
    };

    stageKV(0, 0);

    // Q group drained (KV0 may still be in flight); fragments are loop-invariant
    CP_WAIT(1);
    __syncthreads();
    unsigned qfr[4][4];
#pragma unroll
    for (int s = 0; s < 4; s++)
        ldsm_x4(qfr[s], smem0 + qr * SPH * 2 + s * 32 + a_off);

    float lacc[4] = {0.f, 0.f, 0.f, 0.f};
    float oacc[8][4];
#pragma unroll
    for (int j = 0; j < 8; j++)
#pragma unroll
        for (int k = 0; k < 4; k++) oacc[j][k] = 0.f;

    const int NKT = TT / 128;
    for (int kt = 0; kt < NKT; kt++) {
        CP_WAIT(0);          // only KV(kt) can be pending here
        __syncthreads();     // visibility + protects buffer being restaged
        if (kt + 1 < NKT) stageKV(kt + 1, (kt + 1) & 1);

        const unsigned ksu = smem0 + (128 + (kt & 1) * 128) * SPH * 2;
        const unsigned vsu = smem0 + (384 + (kt & 1) * 128) * SPH * 2;

#pragma unroll
        for (int hf = 0; hf < 2; hf++) {
            const unsigned ksu_h = ksu + hf * 64 * SPH * 2;
            const unsigned vsu_h = vsu + hf * 64 * SPH * 2;

            // ---- S = Q K^T ----
            float sacc[8][4];
#pragma unroll
            for (int j = 0; j < 8; j++)
#pragma unroll
                for (int k = 0; k < 4; k++) sacc[j][k] = 0.f;

#pragma unroll
            for (int s = 0; s < 4; s++) {
                const unsigned kb2 = s * 16 * 2;
#pragma unroll
                for (int jp = 0; jp < 4; jp++) {
                    unsigned bq[4];
                    ldsm_x4(bq, ksu_h + jp * 16 * SPH * 2 + kb2 + b4_off);
                    mma_f16(sacc[2 * jp],     qfr[s], bq[0], bq[1]);
                    mma_f16(sacc[2 * jp + 1], qfr[s], bq[2], bq[3]);
                }
            }

            // ---- p = 2^s packed into PV A-fragments (registers) ----
            unsigned ph[8][2];
#pragma unroll
            for (int j = 0; j < 8; j++) {
                float p0 = ex2f(sacc[j][0]);
                float p1 = ex2f(sacc[j][1]);
                float p2 = ex2f(sacc[j][2]);
                float p3 = ex2f(sacc[j][3]);
                __half2 h01 = __floats2half2_rn(p0, p1);
                __half2 h23 = __floats2half2_rn(p2, p3);
                ph[j][0] = *reinterpret_cast<unsigned*>(&h01);
                ph[j][1] = *reinterpret_cast<unsigned*>(&h23);
            }

            // ---- O += P V, and l += P . 1 (ones-column mma) ----
#pragma unroll
            for (int s = 0; s < 4; s++) {
                const unsigned kb2 = s * 16 * 2;
                unsigned af[4] = {ph[2 * s][0], ph[2 * s][1],
                                  ph[2 * s + 1][0], ph[2 * s + 1][1]};
                mma_f16(lacc, af, bone, bone);
#pragma unroll
                for (int jp = 0; jp < 4; jp++) {
                    unsigned bq[4];
                    ldsm_x4(bq, vsu_h + jp * 16 * SPH * 2 + kb2 + b4_off);
                    mma_f16(oacc[2 * jp],     af, bq[0], bq[1]);
                    mma_f16(oacc[2 * jp + 1], af, bq[2], bq[3]);
                }
            }
        }
    }

    // ---- l lives in col 0 (lanes t==0): broadcast within each quad ----
    const float l0 = __shfl_sync(0xffffffffu, lacc[0], 0, 4);
    const float l1 = __shfl_sync(0xffffffffu, lacc[2], 0, 4);
    const float i0 = 1.0f / l0;
    const float i1 = 1.0f / l1;
    const size_t row0 = (size_t)(b * TT + q0 + qr + g) * DD + h * HD;
    const size_t row1 = row0 + 8 * DD;
#pragma unroll
    for (int j = 0; j < 8; j++) {
        *reinterpret_cast<__half2*>(&g_attnh[row0 + j * 8 + 2 * t]) =
            __floats2half2_rn(oacc[j][0] * i0, oacc[j][1] * i0);
        *reinterpret_cast<__half2*>(&g_attnh[row1 + j * 8 + 2 * t]) =
            __floats2half2_rn(oacc[j][2] * i1, oacc[j][3] * i1);
    }
}

// ---------------------------------------------------------------------------
extern "C" void kernel_launch(void* const* d_in, const int* in_sizes, int n_in,
                              void* d_out, int out_size)
{
    const float* x     = (const float*)d_in[0];
    const float* q     = (const float*)d_in[1];
    const float* kv_w  = (const float*)d_in[2];
    const float* kv_b  = (const float*)d_in[3];
    const float* out_w = (const float*)d_in[4];
    const float* out_b = (const float*)d_in[5];
    float* out = (float*)d_out;

    __half *xh, *qh, *wTh, *owTh, *kvh, *attnh;
    cudaGetSymbolAddress((void**)&xh, g_xh);
    cudaGetSymbolAddress((void**)&qh, g_qh);
    cudaGetSymbolAddress((void**)&wTh, g_wTh);
    cudaGetSymbolAddress((void**)&owTh, g_owTh);
    cudaGetSymbolAddress((void**)&kvh, g_kvh);
    cudaGetSymbolAddress((void**)&attnh, g_attnh);

    cudaFuncSetAttribute(gemm_h_kernel,
                         cudaFuncAttributeMaxDynamicSharedMemorySize,
                         (int)GEMM_SMEM);
    cudaFuncSetAttribute(attn_h_kernel,
                         cudaFuncAttributeMaxDynamicSharedMemorySize,
                         (int)ATTN_SMEM);

    // 0) fused conversions: x + q(scaled), and both weight transposes
    {
        const int thr = 256;
        const int n4 = MTOT * DD / 4;
        conv2_kernel<<<(2 * n4 + thr - 1) / thr, thr>>>(
            x, xh, q, qh, n4, 0.125f * 1.44269504f);
        dim3 blk(32, 8);
        convT2_kernel<<<dim3(2 * DD / 32 + DD / 32, DD / 32), blk>>>(
            kv_w, wTh, 2 * DD, out_w, owTh, DD, DD);
    }
    // 1) KV projection (half output feeds attention)
    {
        dim3 grid(2 * DD / 128, MTOT / 128);
        gemm_h_kernel<<<grid, 256, GEMM_SMEM>>>(xh, wTh, kv_b, nullptr, kvh,
                                                MTOT, 2 * DD, DD, 1);
    }
    // 1b) V transpose -> g_vTh[bh][d][kv]
    {
        dim3 blk(32, 8);
        vtrans_kernel<<<dim3(TT / 32, BB * HH * 2), blk>>>();
    }
    // 2) attention (fp16 mma flash, register P, ones-mma l, 1 sync/tile)
    {
        dim3 grid(TT / 128, BB * HH);
        attn_h_kernel<<<grid, 256, ATTN_SMEM>>>();
    }
    // 3) output projection (f32 output)
    {
        dim3 grid(DD / 128, MTOT / 128);
        gemm_h_kernel<<<grid, 256, GEMM_SMEM>>>(attnh, owTh, out_b, out, nullptr,
                                                MTOT, DD, DD, 0);
    }
}

// round 17
// speedup vs baseline: 1.0153x; 1.0153x over previous
#include <cuda_runtime.h>
#include <cuda_fp16.h>
#include <math.h>

#define BB 2
#define TT 2048
#define DD 1024
#define HH 16
#define HD 64
#define MTOT (BB * TT)          // 4096 rows

// Scratch (device globals — no runtime allocation allowed). All half.
__device__ __half g_xh[(size_t)MTOT * DD];          // half(x)
__device__ __half g_qh[(size_t)MTOT * DD];          // half(q * 0.125*log2e)
__device__ __half g_wTh[(size_t)(2 * DD) * DD];     // half(kv_w)^T  [2048][1024]
__device__ __half g_owTh[(size_t)DD * DD];          // half(out_w)^T [1024][1024]
__device__ __half g_kvh[(size_t)MTOT * 2 * DD];     // [4096][2048] (k|v) half
__device__ __half g_attnh[(size_t)MTOT * DD];       // attention out, half

// ---------------------------------------------------------------------------
// helpers (baseline PTX only)
// ---------------------------------------------------------------------------
__device__ __forceinline__ void mma_f16(float c[4], const unsigned a[4],
                                        const unsigned b0, const unsigned b1) {
    asm volatile(
        "mma.sync.aligned.m16n8k16.row.col.f32.f16.f16.f32 "
        "{%0,%1,%2,%3}, {%4,%5,%6,%7}, {%8,%9}, {%0,%1,%2,%3};"
        : "+f"(c[0]), "+f"(c[1]), "+f"(c[2]), "+f"(c[3])
        : "r"(a[0]), "r"(a[1]), "r"(a[2]), "r"(a[3]),
          "r"(b0), "r"(b1));
}

__device__ __forceinline__ void ldsm_x4(unsigned r[4], unsigned saddr) {
    asm volatile("ldmatrix.sync.aligned.m8n8.x4.shared.b16 {%0,%1,%2,%3}, [%4];"
                 : "=r"(r[0]), "=r"(r[1]), "=r"(r[2]), "=r"(r[3]) : "r"(saddr));
}
__device__ __forceinline__ void ldsm_x4t(unsigned r[4], unsigned saddr) {
    asm volatile(
        "ldmatrix.sync.aligned.m8n8.x4.trans.shared.b16 {%0,%1,%2,%3}, [%4];"
        : "=r"(r[0]), "=r"(r[1]), "=r"(r[2]), "=r"(r[3]) : "r"(saddr));
}

__device__ __forceinline__ float ex2f(float x) {
    float y;
    asm("ex2.approx.f32 %0, %1;" : "=f"(y) : "f"(x));
    return y;
}

__device__ __forceinline__ void cp16(void* smem_ptr, const void* gmem) {
    unsigned s = (unsigned)__cvta_generic_to_shared(smem_ptr);
    asm volatile("cp.async.cg.shared.global [%0], [%1], 16;"
                 :: "r"(s), "l"(gmem) : "memory");
}
#define CP_COMMIT() asm volatile("cp.async.commit_group;" ::: "memory")
#define CP_WAIT(n)  asm volatile("cp.async.wait_group %0;" :: "n"(n) : "memory")

// ---------------------------------------------------------------------------
// fused f32 -> f16 conversion: first n4 float4s from inA (scale 1),
// next n4 from inB (scale sc).
// ---------------------------------------------------------------------------
__global__ __launch_bounds__(256) void conv2_kernel(
    const float* __restrict__ inA, __half* __restrict__ outA,
    const float* __restrict__ inB, __half* __restrict__ outB,
    int n4, float sc)
{
    int i = blockIdx.x * blockDim.x + threadIdx.x;
    if (i < n4) {
        float4 v = reinterpret_cast<const float4*>(inA)[i];
        reinterpret_cast<__half2*>(outA)[2 * i] = __floats2half2_rn(v.x, v.y);
        reinterpret_cast<__half2*>(outA)[2 * i + 1] = __floats2half2_rn(v.z, v.w);
    } else if (i < 2 * n4) {
        int j = i - n4;
        float4 v = reinterpret_cast<const float4*>(inB)[j];
        reinterpret_cast<__half2*>(outB)[2 * j] =
            __floats2half2_rn(v.x * sc, v.y * sc);
        reinterpret_cast<__half2*>(outB)[2 * j + 1] =
            __floats2half2_rn(v.z * sc, v.w * sc);
    }
}

// fused transpose+convert for both weights: blockIdx.x < CA/32 -> A (R x CA),
// else B (R x CB). out[c][r] = half(in[r][c]).
__global__ __launch_bounds__(256) void convT2_kernel(
    const float* __restrict__ inA, __half* __restrict__ outA, int CA,
    const float* __restrict__ inB, __half* __restrict__ outB, int CB, int R)
{
    __shared__ float tb[32][33];
    const float* in;
    __half* out;
    int c0, C;
    if ((int)blockIdx.x < CA / 32) {
        in = inA; out = outA; C = CA; c0 = blockIdx.x * 32;
    } else {
        in = inB; out = outB; C = CB; c0 = (blockIdx.x - CA / 32) * 32;
    }
    const int r0 = blockIdx.y * 32;
    const int tx = threadIdx.x, ty = threadIdx.y;
#pragma unroll
    for (int i = 0; i < 32; i += 8)
        tb[ty + i][tx] = in[(size_t)(r0 + ty + i) * C + c0 + tx];
    __syncthreads();
#pragma unroll
    for (int i = 0; i < 32; i += 8)
        out[(size_t)(c0 + ty + i) * R + r0 + tx] = __float2half_rn(tb[tx][ty + i]);
}

// ---------------------------------------------------------------------------
// fp16 mma GEMM: C[M,N] = A[M,K] @ Bt[N,K]^T + bias[N]
// CTA 128x128, 8 warps (2m x 4n), warp tile 64x32, K-step 64 halves.
// 3-stage cp.async pipeline, ONE __syncthreads per K-tile.
// ---------------------------------------------------------------------------
#define AH 72
#define GEMM_SMEM (6 * 128 * AH * sizeof(__half))   // 108KB

__global__ __launch_bounds__(256) void gemm_h_kernel(
    const __half* __restrict__ A, const __half* __restrict__ Bt,
    const float* __restrict__ bias, float* __restrict__ Cf,
    __half* __restrict__ Ch, int M, int N, int K, int out_half)
{
    extern __shared__ __align__(16) __half hsm[];
    const unsigned smem0 = (unsigned)__cvta_generic_to_shared(hsm);

    const int tid  = threadIdx.x;
    const int lane = tid & 31;
    const int wid  = tid >> 5;
    const int g = lane >> 2;
    const int t = lane & 3;

    const int row0 = blockIdx.y * 128;
    const int col0 = blockIdx.x * 128;
    const int warp_m = (wid & 1) * 64;
    const int warp_n = (wid >> 1) * 32;

    const unsigned a_off =
        (((lane & 7) + ((lane & 8) ? 8 : 0)) * AH + ((lane & 16) ? 8 : 0)) * 2;
    const unsigned b4_off =
        (((lane & 7) + ((lane & 16) ? 8 : 0)) * AH + ((lane & 8) ? 8 : 0)) * 2;

    float acc[4][4][4];
#pragma unroll
    for (int mi = 0; mi < 4; mi++)
#pragma unroll
        for (int ni = 0; ni < 4; ni++)
#pragma unroll
            for (int k = 0; k < 4; k++) acc[mi][ni][k] = 0.f;

    const int NT = K >> 6;

    auto stage = [&](int kt, int bf) {
        const int kb = kt << 6;
        __half* as = hsm + bf * 128 * AH;
        __half* bs = hsm + (3 + bf) * 128 * AH;
#pragma unroll
        for (int i = 0; i < 4; i++) {
            const int idx = i * 256 + tid;
            const int r = idx >> 3, c = idx & 7;
            cp16(&as[r * AH + c * 8], A + (size_t)(row0 + r) * K + kb + c * 8);
        }
#pragma unroll
        for (int i = 0; i < 4; i++) {
            const int idx = i * 256 + tid;
            const int r = idx >> 3, c = idx & 7;
            cp16(&bs[r * AH + c * 8], Bt + (size_t)(col0 + r) * K + kb + c * 8);
        }
        CP_COMMIT();
    };

    stage(0, 0);
    stage(1, 1);

    int bf = 0, bf2 = 2;
    for (int kt = 0; kt < NT; kt++) {
        if (kt + 1 < NT) { CP_WAIT(1); } else { CP_WAIT(0); }
        __syncthreads();
        if (kt + 2 < NT) stage(kt + 2, bf2);

        const unsigned asu = smem0 + bf * (128 * AH * 2);
        const unsigned bsu = smem0 + (3 + bf) * (128 * AH * 2);

#pragma unroll
        for (int s = 0; s < 4; s++) {
            const unsigned kb2 = s * 16 * 2;
            unsigned afr[4][4];
#pragma unroll
            for (int mi = 0; mi < 4; mi++)
                ldsm_x4(afr[mi],
                        asu + (warp_m + mi * 16) * AH * 2 + kb2 + a_off);
            unsigned bfr[2][4];
#pragma unroll
            for (int np = 0; np < 2; np++)
                ldsm_x4(bfr[np],
                        bsu + (warp_n + np * 16) * AH * 2 + kb2 + b4_off);
#pragma unroll
            for (int mi = 0; mi < 4; mi++)
#pragma unroll
                for (int ni = 0; ni < 4; ni++)
                    mma_f16(acc[mi][ni], afr[mi],
                            bfr[ni >> 1][(ni & 1) * 2],
                            bfr[ni >> 1][(ni & 1) * 2 + 1]);
        }
        bf = (bf == 2) ? 0 : bf + 1;
        bf2 = (bf2 == 2) ? 0 : bf2 + 1;
    }

#pragma unroll
    for (int ni = 0; ni < 4; ni++) {
        const int col = col0 + warp_n + ni * 8 + 2 * t;
        const float b0 = bias[col], b1 = bias[col + 1];
#pragma unroll
        for (int mi = 0; mi < 4; mi++) {
            const int row = row0 + warp_m + mi * 16 + g;
            float v00 = acc[mi][ni][0] + b0, v01 = acc[mi][ni][1] + b1;
            float v10 = acc[mi][ni][2] + b0, v11 = acc[mi][ni][3] + b1;
            if (out_half) {
                *reinterpret_cast<__half2*>(Ch + (size_t)row * N + col) =
                    __floats2half2_rn(v00, v01);
                *reinterpret_cast<__half2*>(Ch + (size_t)(row + 8) * N + col) =
                    __floats2half2_rn(v10, v11);
            } else {
                *reinterpret_cast<float2*>(Cf + (size_t)row * N + col) =
                    make_float2(v00, v01);
                *reinterpret_cast<float2*>(Cf + (size_t)(row + 8) * N + col) =
                    make_float2(v10, v11);
            }
        }
    }
}

// ---------------------------------------------------------------------------
// fp16 mma flash attention: register-resident P, hoisted Q fragments,
// no-max softmax (p = 2^s), l via ones-column MMA, 128-key big tiles,
// V consumed in natural [kv][d] layout via ldmatrix.trans (no vT scratch),
// paired-x4 B loads, cp.async double buffer, ONE sync per tile.
// Grid: (Tq/128, B*H). 8 warps; warp w owns q rows [16w,16w+16).
// smem: Q(128) + K(2x128) + V(2x128) rows, pitch 72 halves = 90KB.
// ---------------------------------------------------------------------------
#define SPH 72
#define ATTN_SMEM ((size_t)(128 + 256 + 256) * SPH * sizeof(__half))

__global__ __launch_bounds__(256) void attn_h_kernel()
{
    extern __shared__ __align__(16) __half sm[];
    __half* Qs     = sm;                     // [128][SPH]
    __half* Ksb[2] = {Qs + 128 * SPH, Qs + 256 * SPH};   // each [128][SPH] (kv x d)
    __half* Vsb[2] = {Qs + 384 * SPH, Qs + 512 * SPH};   // each [128][SPH] (kv x d)
    const unsigned smem0 = (unsigned)__cvta_generic_to_shared(sm);

    const int bh = blockIdx.y;
    const int b  = bh >> 4;
    const int h  = bh & 15;
    const int q0 = blockIdx.x * 128;

    const int tid  = threadIdx.x;
    const int wid  = tid >> 5;
    const int lane = tid & 31;
    const int g = lane >> 2;
    const int t = lane & 3;
    const int qr = wid * 16;

    // A-style offset: rows = 16-group (lane&7 | lane&8), col +8 on lane&16.
    // Used for Q/A fragments AND for V trans loads (rows = kv, col = d pair).
    const unsigned a_off =
        (((lane & 7) + ((lane & 8) ? 8 : 0)) * SPH + ((lane & 16) ? 8 : 0)) * 2;
    // K paired-x4 (non-trans): rows = n-tile pair (lane&7 | lane&16), k+8 on lane&8
    const unsigned b4_off =
        (((lane & 7) + ((lane & 16) ? 8 : 0)) * SPH + ((lane & 8) ? 8 : 0)) * 2;

    const unsigned bone = (g == 0) ? 0x3C003C00u : 0u;

    // ---- stage Q tile (own cp.async group) ----
#pragma unroll
    for (int i = 0; i < 4; i++) {
        const int idx = i * 256 + tid;
        const int r = idx >> 3, c = idx & 7;
        cp16(&Qs[r * SPH + c * 8],
             g_qh + (size_t)(b * TT + q0 + r) * DD + h * HD + c * 8);
    }
    CP_COMMIT();

    // stage one 128-key big tile: K rows and V rows both natural [kv][d]
    auto stageKV = [&](int kt, int bf) {
        const int k0 = kt * 128;
#pragma unroll
        for (int i = 0; i < 4; i++) {
            const int idx = i * 256 + tid;
            const int r = idx >> 3, c = idx & 7;     // r: 0..127
            const __half* src =
                g_kvh + (size_t)(b * TT + k0 + r) * (2 * DD) + h * HD + c * 8;
            cp16(&Ksb[bf][r * SPH + c * 8], src);
            cp16(&Vsb[bf][r * SPH + c * 8], src + DD);
        }
        CP_COMMIT();
    };

    stageKV(0, 0);

    // Q group drained (KV0 may still be in flight); fragments are loop-invariant
    CP_WAIT(1);
    __syncthreads();
    unsigned qfr[4][4];
#pragma unroll
    for (int s = 0; s < 4; s++)
        ldsm_x4(qfr[s], smem0 + qr * SPH * 2 + s * 32 + a_off);

    float lacc[4] = {0.f, 0.f, 0.f, 0.f};
    float oacc[8][4];
#pragma unroll
    for (int j = 0; j < 8; j++)
#pragma unroll
        for (int k = 0; k < 4; k++) oacc[j][k] = 0.f;

    const int NKT = TT / 128;
    for (int kt = 0; kt < NKT; kt++) {
        CP_WAIT(0);          // only KV(kt) can be pending here
        __syncthreads();     // visibility + protects buffer being restaged
        if (kt + 1 < NKT) stageKV(kt + 1, (kt + 1) & 1);

        const unsigned ksu = smem0 + (128 + (kt & 1) * 128) * SPH * 2;
        const unsigned vsu = smem0 + (384 + (kt & 1) * 128) * SPH * 2;

#pragma unroll
        for (int hf = 0; hf < 2; hf++) {
            const unsigned ksu_h = ksu + hf * 64 * SPH * 2;
            const unsigned vsu_h = vsu + hf * 64 * SPH * 2;

            // ---- S = Q K^T ----
            float sacc[8][4];
#pragma unroll
            for (int j = 0; j < 8; j++)
#pragma unroll
                for (int k = 0; k < 4; k++) sacc[j][k] = 0.f;

#pragma unroll
            for (int s = 0; s < 4; s++) {
                const unsigned kb2 = s * 16 * 2;
#pragma unroll
                for (int jp = 0; jp < 4; jp++) {
                    unsigned bq[4];
                    ldsm_x4(bq, ksu_h + jp * 16 * SPH * 2 + kb2 + b4_off);
                    mma_f16(sacc[2 * jp],     qfr[s], bq[0], bq[1]);
                    mma_f16(sacc[2 * jp + 1], qfr[s], bq[2], bq[3]);
                }
            }

            // ---- p = 2^s packed into PV A-fragments (registers) ----
            unsigned ph[8][2];
#pragma unroll
            for (int j = 0; j < 8; j++) {
                float p0 = ex2f(sacc[j][0]);
                float p1 = ex2f(sacc[j][1]);
                float p2 = ex2f(sacc[j][2]);
                float p3 = ex2f(sacc[j][3]);
                __half2 h01 = __floats2half2_rn(p0, p1);
                __half2 h23 = __floats2half2_rn(p2, p3);
                ph[j][0] = *reinterpret_cast<unsigned*>(&h01);
                ph[j][1] = *reinterpret_cast<unsigned*>(&h23);
            }

            // ---- O += P V (V via trans ldsm from [kv][d]), l += P . 1 ----
#pragma unroll
            for (int s = 0; s < 4; s++) {
                const unsigned kb2 = s * 16 * SPH * 2;   // kv-row base
                unsigned af[4] = {ph[2 * s][0], ph[2 * s][1],
                                  ph[2 * s + 1][0], ph[2 * s + 1][1]};
                mma_f16(lacc, af, bone, bone);
#pragma unroll
                for (int jp = 0; jp < 4; jp++) {
                    unsigned bq[4];
                    ldsm_x4t(bq, vsu_h + kb2 + jp * 32 + a_off);
                    mma_f16(oacc[2 * jp],     af, bq[0], bq[1]);
                    mma_f16(oacc[2 * jp + 1], af, bq[2], bq[3]);
                }
            }
        }
    }

    // ---- l lives in col 0 (lanes t==0): broadcast within each quad ----
    const float l0 = __shfl_sync(0xffffffffu, lacc[0], 0, 4);
    const float l1 = __shfl_sync(0xffffffffu, lacc[2], 0, 4);
    const float i0 = 1.0f / l0;
    const float i1 = 1.0f / l1;
    const size_t row0 = (size_t)(b * TT + q0 + qr + g) * DD + h * HD;
    const size_t row1 = row0 + 8 * DD;
#pragma unroll
    for (int j = 0; j < 8; j++) {
        *reinterpret_cast<__half2*>(&g_attnh[row0 + j * 8 + 2 * t]) =
            __floats2half2_rn(oacc[j][0] * i0, oacc[j][1] * i0);
        *reinterpret_cast<__half2*>(&g_attnh[row1 + j * 8 + 2 * t]) =
            __floats2half2_rn(oacc[j][2] * i1, oacc[j][3] * i1);
    }
}

// ---------------------------------------------------------------------------
extern "C" void kernel_launch(void* const* d_in, const int* in_sizes, int n_in,
                              void* d_out, int out_size)
{
    const float* x     = (const float*)d_in[0];
    const float* q     = (const float*)d_in[1];
    const float* kv_w  = (const float*)d_in[2];
    const float* kv_b  = (const float*)d_in[3];
    const float* out_w = (const float*)d_in[4];
    const float* out_b = (const float*)d_in[5];
    float* out = (float*)d_out;

    __half *xh, *qh, *wTh, *owTh, *kvh, *attnh;
    cudaGetSymbolAddress((void**)&xh, g_xh);
    cudaGetSymbolAddress((void**)&qh, g_qh);
    cudaGetSymbolAddress((void**)&wTh, g_wTh);
    cudaGetSymbolAddress((void**)&owTh, g_owTh);
    cudaGetSymbolAddress((void**)&kvh, g_kvh);
    cudaGetSymbolAddress((void**)&attnh, g_attnh);

    cudaFuncSetAttribute(gemm_h_kernel,
                         cudaFuncAttributeMaxDynamicSharedMemorySize,
                         (int)GEMM_SMEM);
    cudaFuncSetAttribute(attn_h_kernel,
                         cudaFuncAttributeMaxDynamicSharedMemorySize,
                         (int)ATTN_SMEM);

    // 0) fused conversions: x + q(scaled), and both weight transposes
    {
        const int thr = 256;
        const int n4 = MTOT * DD / 4;
        conv2_kernel<<<(2 * n4 + thr - 1) / thr, thr>>>(
            x, xh, q, qh, n4, 0.125f * 1.44269504f);
        dim3 blk(32, 8);
        convT2_kernel<<<dim3(2 * DD / 32 + DD / 32, DD / 32), blk>>>(
            kv_w, wTh, 2 * DD, out_w, owTh, DD, DD);
    }
    // 1) KV projection (half output feeds attention)
    {
        dim3 grid(2 * DD / 128, MTOT / 128);
        gemm_h_kernel<<<grid, 256, GEMM_SMEM>>>(xh, wTh, kv_b, nullptr, kvh,
                                                MTOT, 2 * DD, DD, 1);
    }
    // 2) attention (fp16 mma flash; V direct via ldmatrix.trans)
    {
        dim3 grid(TT / 128, BB * HH);
        attn_h_kernel<<<grid, 256, ATTN_SMEM>>>();
    }
    // 3) output projection (f32 output)
    {
        dim3 grid(DD / 128, MTOT / 128);
        gemm_h_kernel<<<grid, 256, GEMM_SMEM>>>(attnh, owTh, out_b, out, nullptr,
                                                MTOT, DD, DD, 0);
    }
}